// round 2
// baseline (speedup 1.0000x reference)
#include <cuda_runtime.h>
#include <cuda_bf16.h>
#include <math.h>

#define NFR    65536
#define DIM    512
#define HEADS  8
#define ATTR   256
#define XDIM   768
#define KSTEPS 16
#define SCALE  0.125f
#define GRID23 148

// ------------------------- static device scratch -------------------------
__device__ __align__(16) float g_Wck[DIM*DIM];          // W_ctx @ Wk
__device__ __align__(16) float g_Wcv[DIM*DIM];          // W_ctx @ Wv
__device__ __align__(16) float g_A[HEADS*DIM*DIM];      // [h][i][j]
__device__ __align__(16) float g_Bt[DIM*HEADS*DIM];     // [j][h*512+i]
__device__ __align__(16) float g_cvec[HEADS*DIM];       // scale*Wck_hb@bq_hb
__device__ __align__(16) float g_bo2[DIM];
__device__ __align__(16) float g_colsum[DIM];
__device__ __align__(16) float g_h[2][DIM];
__device__ __align__(16) float g_u[HEADS*DIM];          // [h][i]
__device__ __align__(16) float g_x[XDIM];               // [a_prev ; ctxo]
__device__ __align__(16) float g_ihh[3072];             // [ih(1536) ; hh(1536)]
__device__ __align__(16) float g_la[NFR*HEADS];         // logits [n][h]
__device__ __align__(16) float g_wpart[GRID23*4096];    // per-block w partials
__device__ unsigned g_maxbits[HEADS];
__device__ float    g_sumexp[HEADS];

__device__ __forceinline__ unsigned encf(float f){
    unsigned u = __float_as_uint(f);
    return (u & 0x80000000u) ? ~u : (u | 0x80000000u);
}
__device__ __forceinline__ float decf(unsigned e){
    unsigned u = (e & 0x80000000u) ? (e ^ 0x80000000u) : ~e;
    return __uint_as_float(u);
}
__device__ __forceinline__ float wred(float a){
    #pragma unroll
    for (int o = 16; o; o >>= 1) a += __shfl_xor_sync(0xffffffffu, a, o);
    return a;
}

// ------------------------------ setup ------------------------------------
__global__ void p0_zero(){
    g_colsum[threadIdx.x] = 0.0f;
}

__global__ void p1_colsum(const float4* __restrict__ F4){
    int t = threadIdx.x;                    // 128 threads -> 128 float4 cols
    float4 acc = make_float4(0.f,0.f,0.f,0.f);
    size_t r0 = (size_t)blockIdx.x * (NFR/128);
    for (int r = 0; r < NFR/128; r++){
        float4 f = F4[(r0 + r)*128 + t];
        acc.x += f.x; acc.y += f.y; acc.z += f.z; acc.w += f.w;
    }
    atomicAdd(&g_colsum[t*4+0], acc.x);
    atomicAdd(&g_colsum[t*4+1], acc.y);
    atomicAdd(&g_colsum[t*4+2], acc.z);
    atomicAdd(&g_colsum[t*4+3], acc.w);
}

// Wck = W_ctx@Wk (z=0), Wcv = W_ctx@Wv (z=1)
__global__ void p2_gemm(const float* __restrict__ Wctx,
                        const float* __restrict__ Wk,
                        const float* __restrict__ Wv){
    __shared__ float sA[32][33];
    __shared__ float sB[32][33];
    int tx = threadIdx.x, ty = threadIdx.y;
    const float* B = blockIdx.z ? Wv : Wk;
    float* O = blockIdx.z ? g_Wcv : g_Wck;
    int i0 = blockIdx.y*32, j0 = blockIdx.x*32;
    float acc[4] = {0.f,0.f,0.f,0.f};
    for (int m0 = 0; m0 < DIM; m0 += 32){
        #pragma unroll
        for (int k = 0; k < 4; k++){
            sA[ty+8*k][tx] = Wctx[(size_t)(i0+ty+8*k)*DIM + m0+tx];
            sB[ty+8*k][tx] = B[(size_t)(m0+ty+8*k)*DIM + j0+tx];
        }
        __syncthreads();
        #pragma unroll
        for (int mm = 0; mm < 32; mm++){
            float b = sB[mm][tx];
            #pragma unroll
            for (int k = 0; k < 4; k++) acc[k] += sA[ty+8*k][mm]*b;
        }
        __syncthreads();
    }
    #pragma unroll
    for (int k = 0; k < 4; k++)
        O[(size_t)(i0+ty+8*k)*DIM + j0+tx] = acc[k];
}

// z<8: A_h = scale*Wck[:,hb]@Wq[:,hb]^T ; z>=8: Bt[j][h*512+i] = Wcv[:,hb]@Wo[hb,:]
__global__ void p3_AB(const float* __restrict__ Wq, const float* __restrict__ Wo){
    __shared__ float sA[32][65];
    __shared__ float sB[32][65];
    int tx = threadIdx.x, ty = threadIdx.y;
    int tid = ty*32 + tx;
    int z = blockIdx.z;
    if (z < 8){
        int h = z, i0 = blockIdx.y*32, j0 = blockIdx.x*32;
        for (int e = tid; e < 2048; e += 256){
            int r = e >> 6, d = e & 63;
            sA[r][d] = g_Wck[(size_t)(i0+r)*DIM + h*64 + d];
            sB[r][d] = Wq[(size_t)(j0+r)*DIM + h*64 + d];
        }
        __syncthreads();
        float acc[4] = {0.f,0.f,0.f,0.f};
        #pragma unroll 8
        for (int d = 0; d < 64; d++){
            float b = sB[tx][d];
            #pragma unroll
            for (int k = 0; k < 4; k++) acc[k] += sA[ty+8*k][d]*b;
        }
        #pragma unroll
        for (int k = 0; k < 4; k++)
            g_A[(size_t)(h*DIM + i0+ty+8*k)*DIM + j0+tx] = SCALE*acc[k];
    } else {
        int h = z-8, i0 = blockIdx.x*32, j0 = blockIdx.y*32;
        for (int e = tid; e < 2048; e += 256){
            int r = e >> 6, d = e & 63;
            sA[r][d] = g_Wcv[(size_t)(i0+r)*DIM + h*64 + d];
        }
        for (int e = tid; e < 2048; e += 256){
            int j = e & 31, d = e >> 5;
            sB[j][d] = Wo[(size_t)(h*64+d)*DIM + j0 + j];
        }
        __syncthreads();
        float acc[4] = {0.f,0.f,0.f,0.f};
        #pragma unroll 8
        for (int d = 0; d < 64; d++){
            float a = sA[tx][d];
            #pragma unroll
            for (int k = 0; k < 4; k++) acc[k] += a*sB[ty+8*k][d];
        }
        #pragma unroll
        for (int k = 0; k < 4; k++)
            g_Bt[(size_t)(j0+ty+8*k)*4096 + h*DIM + i0 + tx] = acc[k];
    }
}

__global__ void p4_vec(const float* __restrict__ Wctx, const float* __restrict__ bctx,
                       const float* __restrict__ Wv,   const float* __restrict__ bv,
                       const float* __restrict__ Wo,   const float* __restrict__ bo,
                       const float* __restrict__ bq,   const float* __restrict__ start){
    __shared__ float bvp[DIM];
    int t = threadIdx.x;                       // 512
    float s = 0.f;
    for (int i = 0; i < DIM; i++) s += bctx[i]*Wv[(size_t)i*DIM + t];
    bvp[t] = s + bv[t];
    __syncthreads();
    float s2 = 0.f;
    for (int k = 0; k < DIM; k++) s2 += bvp[k]*Wo[(size_t)k*DIM + t];
    g_bo2[t] = s2 + bo[t];
    float s3 = 0.f;
    const float inv = 1.0f/(float)NFR;
    for (int i = 0; i < DIM; i++) s3 += (g_colsum[i]*inv)*Wctx[(size_t)i*DIM + t];
    g_h[0][t] = s3 + bctx[t];
    for (int r = t; r < HEADS*DIM; r += DIM){
        int h = r >> 9, i = r & 511;
        float s4 = 0.f;
        #pragma unroll 8
        for (int d = 0; d < 64; d++) s4 += g_Wck[(size_t)i*DIM + h*64 + d]*bq[h*64 + d];
        g_cvec[r] = SCALE*s4;
    }
    if (t < ATTR) g_x[t] = start[t];
}

// ----------------------------- per-step ----------------------------------
// u = A@h + cvec ; also zero step accumulators
__global__ void s1_u(int p){
    int gt = blockIdx.x*256 + threadIdx.x;
    if (gt < 8){ g_sumexp[gt] = 0.f; g_maxbits[gt] = 0u; }
    const int warp = threadIdx.x >> 5, lane = threadIdx.x & 31;
    const int gw = blockIdx.x*8 + warp, nw = gridDim.x*8;
    const float4* H4 = (const float4*)g_h[p];
    float4 hv[4];
    #pragma unroll
    for (int k = 0; k < 4; k++) hv[k] = H4[lane + 32*k];
    for (int r = gw; r < HEADS*DIM; r += nw){
        const float4* A4 = (const float4*)(g_A + (size_t)r*DIM);
        float a = 0.f;
        #pragma unroll
        for (int k = 0; k < 4; k++){
            float4 av = A4[lane + 32*k];
            a += av.x*hv[k].x + av.y*hv[k].y + av.z*hv[k].z + av.w*hv[k].w;
        }
        a = wred(a);
        if (lane == 0) g_u[r] = a + g_cvec[r];
    }
}

// pass 1: logits + per-head max
__global__ void __launch_bounds__(256,1) s2_logits(const float4* __restrict__ F4){
    const int warp = threadIdx.x >> 5, lane = threadIdx.x & 31;
    const float4* U4 = (const float4*)g_u;
    float4 u4[8][4];
    #pragma unroll
    for (int h = 0; h < 8; h++)
        #pragma unroll
        for (int k = 0; k < 4; k++) u4[h][k] = U4[h*128 + lane + 32*k];
    float lmax = -3.0e38f;
    const int gw = blockIdx.x*8 + warp, nw = gridDim.x*8;
    for (int n = gw; n < NFR; n += nw){
        const float4* Fr = F4 + (size_t)n*128;
        float4 f0 = Fr[lane], f1 = Fr[lane+32], f2 = Fr[lane+64], f3 = Fr[lane+96];
        float mine = 0.f;
        #pragma unroll
        for (int h = 0; h < 8; h++){
            float a = f0.x*u4[h][0].x + f0.y*u4[h][0].y + f0.z*u4[h][0].z + f0.w*u4[h][0].w
                    + f1.x*u4[h][1].x + f1.y*u4[h][1].y + f1.z*u4[h][1].z + f1.w*u4[h][1].w
                    + f2.x*u4[h][2].x + f2.y*u4[h][2].y + f2.z*u4[h][2].z + f2.w*u4[h][2].w
                    + f3.x*u4[h][3].x + f3.y*u4[h][3].y + f3.z*u4[h][3].z + f3.w*u4[h][3].w;
            a = wred(a);
            if (lane == h) mine = a;
        }
        if (lane < 8){
            g_la[(size_t)n*8 + lane] = mine;
            lmax = fmaxf(lmax, mine);
        }
    }
    if (lane < 8) atomicMax(&g_maxbits[lane], encf(lmax));
}

// pass 2: e = exp(l-max); sumexp; w_h += e*F[n]  (register acc -> smem -> partials)
__global__ void __launch_bounds__(256,1) s3_accw(const float4* __restrict__ F4){
    const int warp = threadIdx.x >> 5, lane = threadIdx.x & 31, tid = threadIdx.x;
    float mx = (lane < 8) ? decf(g_maxbits[lane]) : 0.f;
    float4 acc[8][4];
    #pragma unroll
    for (int h = 0; h < 8; h++)
        #pragma unroll
        for (int k = 0; k < 4; k++) acc[h][k] = make_float4(0.f,0.f,0.f,0.f);
    float esum = 0.f;
    const int gw = blockIdx.x*8 + warp, nw = gridDim.x*8;
    for (int n = gw; n < NFR; n += nw){
        float e = 0.f;
        if (lane < 8) e = __expf(g_la[(size_t)n*8 + lane] - mx);
        const float4* Fr = F4 + (size_t)n*128;
        float4 f0 = Fr[lane], f1 = Fr[lane+32], f2 = Fr[lane+64], f3 = Fr[lane+96];
        esum += e;
        #pragma unroll
        for (int h = 0; h < 8; h++){
            float eh = __shfl_sync(0xffffffffu, e, h);
            acc[h][0].x += eh*f0.x; acc[h][0].y += eh*f0.y; acc[h][0].z += eh*f0.z; acc[h][0].w += eh*f0.w;
            acc[h][1].x += eh*f1.x; acc[h][1].y += eh*f1.y; acc[h][1].z += eh*f1.z; acc[h][1].w += eh*f1.w;
            acc[h][2].x += eh*f2.x; acc[h][2].y += eh*f2.y; acc[h][2].z += eh*f2.z; acc[h][2].w += eh*f2.w;
            acc[h][3].x += eh*f3.x; acc[h][3].y += eh*f3.y; acc[h][3].z += eh*f3.z; acc[h][3].w += eh*f3.w;
        }
    }
    __shared__ __align__(16) float sw[4096];
    __shared__ float ss[8];
    for (int i = tid; i < 4096; i += 256) sw[i] = 0.f;
    if (tid < 8) ss[tid] = 0.f;
    __syncthreads();
    if (lane < 8) atomicAdd(&ss[lane], esum);
    float4* sw4 = (float4*)sw;
    for (int wp = 0; wp < 8; wp++){
        if (warp == wp){
            #pragma unroll
            for (int h = 0; h < 8; h++)
                #pragma unroll
                for (int k = 0; k < 4; k++){
                    float4 v = sw4[h*128 + lane + 32*k];
                    v.x += acc[h][k].x; v.y += acc[h][k].y;
                    v.z += acc[h][k].z; v.w += acc[h][k].w;
                    sw4[h*128 + lane + 32*k] = v;
                }
        }
        __syncthreads();
    }
    float* outp = g_wpart + (size_t)blockIdx.x*4096;
    for (int i = tid; i < 4096; i += 256) outp[i] = sw[i];
    if (tid < 8) atomicAdd(&g_sumexp[tid], ss[tid]);
}

// ctxo = sum_h (w_h/s_h)@B_h + bo2  -> g_x[256:768]
__global__ void s4_ctxo(){
    __shared__ __align__(16) float sw[4096];
    const int tid = threadIdx.x;
    for (int i = tid; i < 4096; i += 256){
        float s = 0.f;
        #pragma unroll 4
        for (int b = 0; b < GRID23; b++) s += g_wpart[(size_t)b*4096 + i];
        sw[i] = s * (1.0f/g_sumexp[i >> 9]);
    }
    __syncthreads();
    const int warp = tid >> 5, lane = tid & 31;
    const int gw = blockIdx.x*8 + warp;        // 16 blocks -> 128 warps
    const float4* SW4 = (const float4*)sw;
    for (int j = gw; j < DIM; j += 128){
        const float4* B4 = (const float4*)(g_Bt + (size_t)j*4096);
        float a = 0.f;
        #pragma unroll
        for (int kk = 0; kk < 32; kk++){
            float4 b = B4[lane + 32*kk];
            float4 w = SW4[lane + 32*kk];
            a += b.x*w.x + b.y*w.y + b.z*w.z + b.w*w.w;
        }
        a = wred(a);
        if (lane == 0) g_x[ATTR + j] = a + g_bo2[j];
    }
}

// GRU matvecs: ih = W_ih@x + b_ih ; hh = W_hh@h
__global__ void s5_gru(const float* __restrict__ W_ih, const float* __restrict__ W_hh,
                       const float* __restrict__ b_ih, int p){
    const int warp = threadIdx.x >> 5, lane = threadIdx.x & 31;
    const int gw = blockIdx.x*8 + warp, nw = gridDim.x*8;
    for (int r = gw; r < 3072; r += nw){
        float a = 0.f;
        if (r < 1536){
            const float4* W = (const float4*)(W_ih + (size_t)r*XDIM);
            const float4* X = (const float4*)g_x;
            #pragma unroll
            for (int k = 0; k < 6; k++){
                float4 w = W[lane + 32*k], x = X[lane + 32*k];
                a += w.x*x.x + w.y*x.y + w.z*x.z + w.w*x.w;
            }
            a = wred(a);
            if (lane == 0) g_ihh[r] = a + b_ih[r];
        } else {
            int rr = r - 1536;
            const float4* W = (const float4*)(W_hh + (size_t)rr*DIM);
            const float4* H = (const float4*)g_h[p];
            #pragma unroll
            for (int k = 0; k < 4; k++){
                float4 w = W[lane + 32*k], h = H[lane + 32*k];
                a += w.x*h.x + w.y*h.y + w.z*h.z + w.w*h.w;
            }
            a = wred(a);
            if (lane == 0) g_ihh[r] = a;
        }
    }
}

// gates + heads + output
__global__ void s6_fin(int p, int step, float* __restrict__ out,
                       const float* __restrict__ b_hn,
                       const float* __restrict__ W_attr, const float* __restrict__ b_attr,
                       const float* __restrict__ W_conf, const float* __restrict__ b_conf){
    __shared__ __align__(16) float hn[DIM];
    const int tid = threadIdx.x;
    for (int j = tid; j < DIM; j += 256){
        float ihr = g_ihh[j],        ihz = g_ihh[512+j],  ihn = g_ihh[1024+j];
        float hhr = g_ihh[1536+j],   hhz = g_ihh[2048+j], hhn = g_ihh[2560+j];
        float r = 1.0f/(1.0f + expf(-(ihr + hhr)));
        float z = 1.0f/(1.0f + expf(-(ihz + hhz)));
        float nn = tanhf(ihn + r*(hhn + b_hn[j]));
        float h = (1.0f - z)*nn + z*g_h[p][j];
        hn[j] = h;
        if (blockIdx.x == 0) g_h[1-p][j] = h;
    }
    __syncthreads();
    const int warp = tid >> 5, lane = tid & 31;
    const int gw = blockIdx.x*8 + warp;        // 0..127
    const float4* H4 = (const float4*)hn;
    float4 hv[4];
    #pragma unroll
    for (int k = 0; k < 4; k++) hv[k] = H4[lane + 32*k];
    #pragma unroll
    for (int rr = 0; rr < 2; rr++){
        int row = gw*2 + rr;                   // 0..255
        const float4* W = (const float4*)(W_attr + (size_t)row*DIM);
        float a = 0.f;
        #pragma unroll
        for (int k = 0; k < 4; k++){
            float4 w = W[lane + 32*k];
            a += w.x*hv[k].x + w.y*hv[k].y + w.z*hv[k].z + w.w*hv[k].w;
        }
        a = wred(a);
        if (lane == 0){
            float v = a + b_attr[row];
            out[step*ATTR + row] = v;
            g_x[row] = v;
        }
    }
    if (gw == 0){
        const float4* W = (const float4*)W_conf;
        float a = 0.f;
        #pragma unroll
        for (int k = 0; k < 4; k++){
            float4 w = W[lane + 32*k];
            a += w.x*hv[k].x + w.y*hv[k].y + w.z*hv[k].z + w.w*hv[k].w;
        }
        a = wred(a);
        if (lane == 0)
            out[KSTEPS*ATTR + step] = 1.0f/(1.0f + expf(-(a + b_conf[0])));
    }
}

// ------------------------------- launch -----------------------------------
extern "C" void kernel_launch(void* const* d_in, const int* in_sizes, int n_in,
                              void* d_out, int out_size){
    const float* F      = (const float*)d_in[0];
    const float* Wctx   = (const float*)d_in[1];
    const float* bctx   = (const float*)d_in[2];
    const float* Wq     = (const float*)d_in[3];
    const float* bq     = (const float*)d_in[4];
    const float* Wk     = (const float*)d_in[5];
    // d_in[6] = bk : provably softmax-invariant, unused
    const float* Wv     = (const float*)d_in[7];
    const float* bv     = (const float*)d_in[8];
    const float* Wo     = (const float*)d_in[9];
    const float* bo     = (const float*)d_in[10];
    const float* W_ih   = (const float*)d_in[11];
    const float* W_hh   = (const float*)d_in[12];
    const float* b_ih   = (const float*)d_in[13];
    const float* b_hn   = (const float*)d_in[14];
    const float* start  = (const float*)d_in[15];
    const float* W_attr = (const float*)d_in[16];
    const float* b_attr = (const float*)d_in[17];
    const float* W_conf = (const float*)d_in[18];
    const float* b_conf = (const float*)d_in[19];
    float* out = (float*)d_out;

    p0_zero<<<1, 512>>>();
    p1_colsum<<<128, 128>>>((const float4*)F);
    p2_gemm<<<dim3(16,16,2), dim3(32,8)>>>(Wctx, Wk, Wv);
    p3_AB<<<dim3(16,16,16), dim3(32,8)>>>(Wq, Wo);
    p4_vec<<<1, 512>>>(Wctx, bctx, Wv, bv, Wo, bo, bq, start);

    for (int step = 0; step < KSTEPS; step++){
        int p = step & 1;
        s1_u<<<128, 256>>>(p);
        s2_logits<<<GRID23, 256>>>((const float4*)F);
        s3_accw<<<GRID23, 256>>>((const float4*)F);
        s4_ctxo<<<16, 256>>>();
        s5_gru<<<96, 256>>>(W_ih, W_hh, b_ih, p);
        s6_fin<<<16, 256>>>(p, step, out, b_hn, W_attr, b_attr, W_conf, b_conf);
    }
}

// round 3
// speedup vs baseline: 1.5494x; 1.5494x over previous
#include <cuda_runtime.h>
#include <cuda_bf16.h>
#include <math.h>

#define NFR    65536
#define DIM    512
#define HEADS  8
#define ATTR   256
#define XDIM   768
#define KSTEPS 16
#define SCALE  0.125f
#define GRIDF  148

// ------------------------- static device scratch -------------------------
__device__ __align__(16) __nv_bfloat16 g_Fh[NFR*DIM];     // bf16 frames (64MB)
__device__ __align__(16) float g_WckT[DIM*DIM];           // scale * (W_ctx@Wk)^T  [o][i]
__device__ __align__(16) float g_Wcv [DIM*DIM];           // W_ctx@Wv [i][o]
__device__ __align__(16) float g_Wih2[1536*XDIM];         // [W_ih[:, :256] | W_ih[:,256:]@Wo^T]
__device__ __align__(16) float g_bih2[1536];
__device__ __align__(16) float g_cvec[HEADS*DIM];         // scale*WckT@bq (per head)
__device__ __align__(16) float g_colsum[DIM];
__device__ __align__(16) float g_h[2][DIM];
__device__ __align__(16) float g_u[HEADS*DIM];            // [h][i]
__device__ __align__(16) float g_x[XDIM];                 // [a_prev(256) ; v(512)]
__device__ __align__(16) float g_ihh[3072];
__device__ __align__(16) float g_wpart[GRIDF*4096];       // per-block softmax-weighted sums
__device__ float g_mpart[GRIDF*HEADS];
__device__ float g_spart[GRIDF*HEADS];

__device__ __forceinline__ float wred(float a){
    #pragma unroll
    for (int o = 16; o; o >>= 1) a += __shfl_xor_sync(0xffffffffu, a, o);
    return a;
}

// ------------------------------ setup ------------------------------------
__global__ void p0_zero(){ g_colsum[threadIdx.x] = 0.0f; }

// convert F -> bf16 + column sums
__global__ void p1c(const float4* __restrict__ F4){
    int t = threadIdx.x;                      // 128 threads = 128 float4 cols
    float4 acc = make_float4(0.f,0.f,0.f,0.f);
    size_t r0 = (size_t)blockIdx.x * (NFR/128);
    uint2* out = (uint2*)g_Fh;
    for (int r = 0; r < NFR/128; r++){
        size_t row = r0 + r;
        float4 f = F4[row*128 + t];
        acc.x += f.x; acc.y += f.y; acc.z += f.z; acc.w += f.w;
        uint2 pk;
        pk.x = ((unsigned)__bfloat16_as_ushort(__float2bfloat16_rn(f.y)) << 16)
             |  (unsigned)__bfloat16_as_ushort(__float2bfloat16_rn(f.x));
        pk.y = ((unsigned)__bfloat16_as_ushort(__float2bfloat16_rn(f.w)) << 16)
             |  (unsigned)__bfloat16_as_ushort(__float2bfloat16_rn(f.z));
        out[row*128 + t] = pk;
    }
    atomicAdd(&g_colsum[t*4+0], acc.x);
    atomicAdd(&g_colsum[t*4+1], acc.y);
    atomicAdd(&g_colsum[t*4+2], acc.z);
    atomicAdd(&g_colsum[t*4+3], acc.w);
}

// z=0: WckT = scale*(W_ctx@Wk)^T ; z=1: Wcv = W_ctx@Wv
__global__ void p2_gemm(const float* __restrict__ Wctx,
                        const float* __restrict__ Wk,
                        const float* __restrict__ Wv){
    __shared__ float sA[32][33];
    __shared__ float sB[32][33];
    int tx = threadIdx.x, ty = threadIdx.y;
    const float* B = blockIdx.z ? Wv : Wk;
    int i0 = blockIdx.y*32, j0 = blockIdx.x*32;
    float acc[4] = {0.f,0.f,0.f,0.f};
    for (int m0 = 0; m0 < DIM; m0 += 32){
        #pragma unroll
        for (int k = 0; k < 4; k++){
            sA[ty+8*k][tx] = Wctx[(size_t)(i0+ty+8*k)*DIM + m0+tx];
            sB[ty+8*k][tx] = B[(size_t)(m0+ty+8*k)*DIM + j0+tx];
        }
        __syncthreads();
        #pragma unroll
        for (int mm = 0; mm < 32; mm++){
            float b = sB[mm][tx];
            #pragma unroll
            for (int k = 0; k < 4; k++) acc[k] += sA[ty+8*k][mm]*b;
        }
        __syncthreads();
    }
    if (blockIdx.z){
        #pragma unroll
        for (int k = 0; k < 4; k++)
            g_Wcv[(size_t)(i0+ty+8*k)*DIM + j0+tx] = acc[k];
    } else {
        // transpose via smem, scale fold, coalesced store
        __syncthreads();
        #pragma unroll
        for (int k = 0; k < 4; k++) sA[tx][ty+8*k] = acc[k];
        __syncthreads();
        #pragma unroll
        for (int k = 0; k < 4; k++)
            g_WckT[(size_t)(j0+ty+8*k)*DIM + i0+tx] = SCALE*sA[ty+8*k][tx];
    }
}

// Wih2: cols [0,256) copy of W_ih ; cols [256,768): W_ih[:,256:] @ Wo^T
__global__ void p3_wih(const float* __restrict__ W_ih, const float* __restrict__ Wo){
    int tx = threadIdx.x, ty = threadIdx.y;
    int i0 = blockIdx.y*32;
    if (blockIdx.x < 16){
        __shared__ float sA[32][33];
        __shared__ float sB[32][33];
        int j0 = blockIdx.x*32;
        float acc[4] = {0.f,0.f,0.f,0.f};
        for (int m0 = 0; m0 < DIM; m0 += 32){
            #pragma unroll
            for (int k = 0; k < 4; k++){
                sA[ty+8*k][tx] = W_ih[(size_t)(i0+ty+8*k)*XDIM + 256 + m0+tx];
                sB[ty+8*k][tx] = Wo[(size_t)(j0+ty+8*k)*DIM + m0+tx];
            }
            __syncthreads();
            #pragma unroll
            for (int mm = 0; mm < 32; mm++){
                float b = sB[tx][mm];
                #pragma unroll
                for (int k = 0; k < 4; k++) acc[k] += sA[ty+8*k][mm]*b;
            }
            __syncthreads();
        }
        #pragma unroll
        for (int k = 0; k < 4; k++)
            g_Wih2[(size_t)(i0+ty+8*k)*XDIM + 256 + j0+tx] = acc[k];
    } else {
        int c0 = (blockIdx.x-16)*32;
        #pragma unroll
        for (int k = 0; k < 4; k++)
            g_Wih2[(size_t)(i0+ty+8*k)*XDIM + c0+tx] =
                W_ih[(size_t)(i0+ty+8*k)*XDIM + c0+tx];
    }
}

__global__ void p4_vec(const float* __restrict__ Wctx, const float* __restrict__ bctx,
                       const float* __restrict__ Wv,   const float* __restrict__ bv,
                       const float* __restrict__ Wo,   const float* __restrict__ bo,
                       const float* __restrict__ bq,   const float* __restrict__ start,
                       const float* __restrict__ W_ih, const float* __restrict__ b_ih){
    __shared__ float bvp[DIM];
    __shared__ float bo2[DIM];
    int t = threadIdx.x;                      // 512
    float s = 0.f;
    for (int i = 0; i < DIM; i++) s += bctx[i]*Wv[(size_t)i*DIM + t];
    bvp[t] = s + bv[t];
    __syncthreads();
    float s2 = 0.f;
    for (int k = 0; k < DIM; k++) s2 += bvp[k]*Wo[(size_t)k*DIM + t];
    bo2[t] = s2 + bo[t];
    __syncthreads();
    float s3 = 0.f;
    const float inv = 1.0f/(float)NFR;
    for (int i = 0; i < DIM; i++) s3 += (g_colsum[i]*inv)*Wctx[(size_t)i*DIM + t];
    g_h[0][t] = s3 + bctx[t];
    // cvec (scale already folded in WckT)
    for (int r = t; r < HEADS*DIM; r += DIM){
        int h = r >> 9, i = r & 511;
        float s4 = 0.f;
        #pragma unroll 8
        for (int d = 0; d < 64; d++)
            s4 += g_WckT[(size_t)(h*64+d)*DIM + i]*bq[h*64 + d];
        g_cvec[r] = s4;
    }
    // bih2 = b_ih + W_ih[:,256:] @ bo2
    for (int r = t; r < 1536; r += DIM){
        float a = b_ih[r];
        for (int j = 0; j < DIM; j++) a += W_ih[(size_t)r*XDIM + 256 + j]*bo2[j];
        g_bih2[r] = a;
    }
    if (t < ATTR) g_x[t] = start[t];
}

// ----------------------------- per-step ----------------------------------
// block h: q_h = Wq_h^T @ h ; u_h = WckT_h @ q_h + cvec_h ; zero v slice
__global__ void s1_u(const float* __restrict__ Wq, int p){
    __shared__ float spq[4][64];
    __shared__ float sq[64];
    const int h = blockIdx.x, tid = threadIdx.x;
    if (tid < 64) g_x[256 + h*64 + tid] = 0.f;
    const int d = tid & 63, ic = tid >> 6;
    float a = 0.f;
    #pragma unroll 4
    for (int ii = 0; ii < 128; ii++){
        int i = ic*128 + ii;
        a += g_h[p][i] * Wq[(size_t)i*DIM + h*64 + d];
    }
    spq[ic][d] = a;
    __syncthreads();
    if (tid < 64) sq[tid] = spq[0][tid]+spq[1][tid]+spq[2][tid]+spq[3][tid];
    __syncthreads();
    for (int i = tid; i < DIM; i += 256){
        float acc = g_cvec[h*DIM + i];
        #pragma unroll 8
        for (int dd = 0; dd < 64; dd++)
            acc += sq[dd]*g_WckT[(size_t)(h*64+dd)*DIM + i];
        g_u[h*DIM + i] = acc;
    }
}

// fused single-pass flash softmax + weighted frame sum (bf16 frames)
__global__ void __launch_bounds__(256,1) s2f(){
    const int tid = threadIdx.x, warp = tid>>5, lane = tid&31;
    const int hside = warp & 1;               // heads [4*hside, 4*hside+4)
    const int pair  = (blockIdx.x<<2) + (warp>>1);
    const int npairs = GRIDF*4;

    __align__(16) float u[4][16];
    __align__(16) float acc[4][16];
    float m[4], s[4];
    #pragma unroll
    for (int hh = 0; hh < 4; hh++){
        const float4* U4 = (const float4*)(g_u + (size_t)(hside*4+hh)*DIM + lane*16);
        #pragma unroll
        for (int k = 0; k < 4; k++) ((float4*)u[hh])[k] = U4[k];
        #pragma unroll
        for (int k = 0; k < 16; k++) acc[hh][k] = 0.f;
        m[hh] = -3.0e38f; s[hh] = 0.f;
    }

    const uint4* F16 = (const uint4*)g_Fh;
    for (int n = pair; n < NFR; n += npairs){
        uint4 r0 = F16[(size_t)n*64 + 2*lane];
        uint4 r1 = F16[(size_t)n*64 + 2*lane + 1];
        float f[16];
        {
            unsigned w;
            w = r0.x; f[0]=__uint_as_float(w<<16); f[1]=__uint_as_float(w&0xffff0000u);
            w = r0.y; f[2]=__uint_as_float(w<<16); f[3]=__uint_as_float(w&0xffff0000u);
            w = r0.z; f[4]=__uint_as_float(w<<16); f[5]=__uint_as_float(w&0xffff0000u);
            w = r0.w; f[6]=__uint_as_float(w<<16); f[7]=__uint_as_float(w&0xffff0000u);
            w = r1.x; f[8]=__uint_as_float(w<<16); f[9]=__uint_as_float(w&0xffff0000u);
            w = r1.y; f[10]=__uint_as_float(w<<16); f[11]=__uint_as_float(w&0xffff0000u);
            w = r1.z; f[12]=__uint_as_float(w<<16); f[13]=__uint_as_float(w&0xffff0000u);
            w = r1.w; f[14]=__uint_as_float(w<<16); f[15]=__uint_as_float(w&0xffff0000u);
        }
        #pragma unroll
        for (int hh = 0; hh < 4; hh++){
            float l = 0.f;
            #pragma unroll
            for (int k = 0; k < 16; k++) l += u[hh][k]*f[k];
            l = wred(l);                         // all lanes hold the logit
            if (l > m[hh]){                      // warp-uniform branch
                float sc = __expf(m[hh] - l);
                s[hh] *= sc;
                #pragma unroll
                for (int k = 0; k < 16; k++) acc[hh][k] *= sc;
                m[hh] = l;
            }
            float e = __expf(l - m[hh]);
            s[hh] += e;
            #pragma unroll
            for (int k = 0; k < 16; k++) acc[hh][k] += e*f[k];
        }
    }

    // block-level combine: align 4 warps per head-group to block max
    __shared__ float smm[8][4], sms[8][4], smb[8];
    __shared__ __align__(16) float sw[4096];
    if (lane == 0){
        #pragma unroll
        for (int hh = 0; hh < 4; hh++) smm[warp][hh] = m[hh];
    }
    __syncthreads();
    if (tid < 8){
        int hs = tid>>2, hh = tid&3;
        float mb = -3.0e38f;
        #pragma unroll
        for (int wp = 0; wp < 4; wp++) mb = fmaxf(mb, smm[wp*2+hs][hh]);
        smb[tid] = mb;
    }
    for (int i = tid; i < 4096; i += 256) sw[i] = 0.f;
    __syncthreads();
    float sc4[4];
    #pragma unroll
    for (int hh = 0; hh < 4; hh++) sc4[hh] = __expf(m[hh] - smb[hside*4+hh]);
    if (lane == 0){
        #pragma unroll
        for (int hh = 0; hh < 4; hh++) sms[warp][hh] = s[hh]*sc4[hh];
    }
    float4* sw4 = (float4*)sw;
    for (int wp = 0; wp < 4; wp++){
        if ((warp>>1) == wp){
            #pragma unroll
            for (int hh = 0; hh < 4; hh++){
                int base = (hside*4+hh)*128 + lane*4;
                #pragma unroll
                for (int k = 0; k < 4; k++){
                    float4 v = sw4[base+k];
                    float4 a = ((float4*)acc[hh])[k];
                    v.x += a.x*sc4[hh]; v.y += a.y*sc4[hh];
                    v.z += a.z*sc4[hh]; v.w += a.w*sc4[hh];
                    sw4[base+k] = v;
                }
            }
        }
        __syncthreads();
    }
    float* op = g_wpart + (size_t)blockIdx.x*4096;
    for (int i = tid; i < 4096; i += 256) op[i] = sw[i];
    if (tid < 8){
        int hs = tid>>2, hh = tid&3;
        float ssum = 0.f;
        #pragma unroll
        for (int wp = 0; wp < 4; wp++) ssum += sms[wp*2+hs][hh];
        g_spart[blockIdx.x*8 + tid] = ssum;
        g_mpart[blockIdx.x*8 + tid] = smb[tid];
    }
}

// combine partials -> c ; v += c@Wcv (into g_x[256:768])
__global__ void s3c(){
    __shared__ float sM[8], sS[8];
    __shared__ float sef[GRIDF*8];
    __shared__ float sc[256];
    __shared__ float sv[4][64];
    const int tid = threadIdx.x, bi = blockIdx.x;
    for (int i = tid; i < GRIDF*8; i += 256) sef[i] = g_mpart[i];
    __syncthreads();
    if (tid < 8){
        float M = -3.0e38f;
        for (int b = 0; b < GRIDF; b++) M = fmaxf(M, sef[b*8+tid]);
        sM[tid] = M;
    }
    __syncthreads();
    for (int i = tid; i < GRIDF*8; i += 256) sef[i] = __expf(sef[i] - sM[i&7]);
    __syncthreads();
    if (tid < 8){
        float S = 0.f;
        for (int b = 0; b < GRIDF; b++) S += g_spart[b*8+tid]*sef[b*8+tid];
        sS[tid] = S;
    }
    __syncthreads();
    const int idx = bi*256 + tid;
    const int hb = bi >> 1;
    {
        float a = 0.f;
        #pragma unroll 4
        for (int b = 0; b < GRIDF; b++) a += g_wpart[(size_t)b*4096 + idx]*sef[b*8+hb];
        sc[tid] = a / sS[hb];
    }
    __syncthreads();
    const int d = tid & 63, isub = tid >> 6;
    const int i0 = (bi & 1)*256;
    float pv = 0.f;
    #pragma unroll 8
    for (int ii = 0; ii < 64; ii++){
        int i = i0 + isub*64 + ii;
        pv += sc[isub*64+ii]*g_Wcv[(size_t)i*DIM + hb*64 + d];
    }
    sv[isub][d] = pv;
    __syncthreads();
    if (tid < 64)
        atomicAdd(&g_x[256 + hb*64 + tid],
                  sv[0][tid]+sv[1][tid]+sv[2][tid]+sv[3][tid]);
}

// GRU matvecs: ih = Wih2@[a;v] + bih2 ; hh = W_hh@h
__global__ void s5_gru(const float* __restrict__ W_hh, int p){
    const int warp = threadIdx.x >> 5, lane = threadIdx.x & 31;
    const int gw = blockIdx.x*8 + warp, nw = gridDim.x*8;
    for (int r = gw; r < 3072; r += nw){
        float a = 0.f;
        if (r < 1536){
            const float4* W = (const float4*)(g_Wih2 + (size_t)r*XDIM);
            const float4* X = (const float4*)g_x;
            #pragma unroll
            for (int k = 0; k < 6; k++){
                float4 w = W[lane + 32*k], x = X[lane + 32*k];
                a += w.x*x.x + w.y*x.y + w.z*x.z + w.w*x.w;
            }
            a = wred(a);
            if (lane == 0) g_ihh[r] = a + g_bih2[r];
        } else {
            int rr = r - 1536;
            const float4* W = (const float4*)(W_hh + (size_t)rr*DIM);
            const float4* H = (const float4*)g_h[p];
            #pragma unroll
            for (int k = 0; k < 4; k++){
                float4 w = W[lane + 32*k], h = H[lane + 32*k];
                a += w.x*h.x + w.y*h.y + w.z*h.z + w.w*h.w;
            }
            a = wred(a);
            if (lane == 0) g_ihh[r] = a;
        }
    }
}

// gates + heads + output
__global__ void s6_fin(int p, int step, float* __restrict__ out,
                       const float* __restrict__ b_hn,
                       const float* __restrict__ W_attr, const float* __restrict__ b_attr,
                       const float* __restrict__ W_conf, const float* __restrict__ b_conf){
    __shared__ __align__(16) float hn[DIM];
    const int tid = threadIdx.x;
    for (int j = tid; j < DIM; j += 256){
        float ihr = g_ihh[j],      ihz = g_ihh[512+j],  ihn = g_ihh[1024+j];
        float hhr = g_ihh[1536+j], hhz = g_ihh[2048+j], hhn = g_ihh[2560+j];
        float r = 1.0f/(1.0f + expf(-(ihr + hhr)));
        float z = 1.0f/(1.0f + expf(-(ihz + hhz)));
        float nn = tanhf(ihn + r*(hhn + b_hn[j]));
        float h = (1.0f - z)*nn + z*g_h[p][j];
        hn[j] = h;
        if (blockIdx.x == 0) g_h[1-p][j] = h;
    }
    __syncthreads();
    const int warp = tid >> 5, lane = tid & 31;
    const int gw = blockIdx.x*8 + warp;        // 0..127
    const float4* H4 = (const float4*)hn;
    float4 hv[4];
    #pragma unroll
    for (int k = 0; k < 4; k++) hv[k] = H4[lane + 32*k];
    #pragma unroll
    for (int rr = 0; rr < 2; rr++){
        int row = gw*2 + rr;                   // 0..255
        const float4* W = (const float4*)(W_attr + (size_t)row*DIM);
        float a = 0.f;
        #pragma unroll
        for (int k = 0; k < 4; k++){
            float4 w = W[lane + 32*k];
            a += w.x*hv[k].x + w.y*hv[k].y + w.z*hv[k].z + w.w*hv[k].w;
        }
        a = wred(a);
        if (lane == 0){
            float v = a + b_attr[row];
            out[step*ATTR + row] = v;
            g_x[row] = v;
        }
    }
    if (gw == 0){
        const float4* W = (const float4*)W_conf;
        float a = 0.f;
        #pragma unroll
        for (int k = 0; k < 4; k++){
            float4 w = W[lane + 32*k];
            a += w.x*hv[k].x + w.y*hv[k].y + w.z*hv[k].z + w.w*hv[k].w;
        }
        a = wred(a);
        if (lane == 0)
            out[KSTEPS*ATTR + step] = 1.0f/(1.0f + expf(-(a + b_conf[0])));
    }
}

// ------------------------------- launch -----------------------------------
extern "C" void kernel_launch(void* const* d_in, const int* in_sizes, int n_in,
                              void* d_out, int out_size){
    const float* F      = (const float*)d_in[0];
    const float* Wctx   = (const float*)d_in[1];
    const float* bctx   = (const float*)d_in[2];
    const float* Wq     = (const float*)d_in[3];
    const float* bq     = (const float*)d_in[4];
    const float* Wk     = (const float*)d_in[5];
    // d_in[6] = bk : softmax-invariant, unused
    const float* Wv     = (const float*)d_in[7];
    const float* bv     = (const float*)d_in[8];
    const float* Wo     = (const float*)d_in[9];
    const float* bo     = (const float*)d_in[10];
    const float* W_ih   = (const float*)d_in[11];
    const float* W_hh   = (const float*)d_in[12];
    const float* b_ih   = (const float*)d_in[13];
    const float* b_hn   = (const float*)d_in[14];
    const float* start  = (const float*)d_in[15];
    const float* W_attr = (const float*)d_in[16];
    const float* b_attr = (const float*)d_in[17];
    const float* W_conf = (const float*)d_in[18];
    const float* b_conf = (const float*)d_in[19];
    float* out = (float*)d_out;

    p0_zero<<<1, 512>>>();
    p1c<<<128, 128>>>((const float4*)F);
    p2_gemm<<<dim3(16,16,2), dim3(32,8)>>>(Wctx, Wk, Wv);
    p3_wih<<<dim3(24,48), dim3(32,8)>>>(W_ih, Wo);
    p4_vec<<<1, 512>>>(Wctx, bctx, Wv, bv, Wo, bo, bq, start, W_ih, b_ih);

    for (int step = 0; step < KSTEPS; step++){
        int p = step & 1;
        s1_u<<<8, 256>>>(Wq, p);
        s2f<<<GRIDF, 256>>>();
        s3c<<<16, 256>>>();
        s5_gru<<<96, 256>>>(W_hh, p);
        s6_fin<<<16, 256>>>(p, step, out, b_hn, W_attr, b_attr, W_conf, b_conf);
    }
}

// round 4
// speedup vs baseline: 1.5583x; 1.0058x over previous
#include <cuda_runtime.h>
#include <cuda_bf16.h>
#include <math.h>

#define NFR    65536
#define DIM    512
#define HEADS  8
#define ATTR   256
#define XDIM   768
#define KSTEPS 16
#define SCALE  0.125f
#define GRIDF  148

// ------------------------- static device scratch -------------------------
__device__ __align__(16) __nv_bfloat16 g_Fh[NFR*DIM];     // bf16 frames (64MB)
__device__ __align__(16) float g_WckT[DIM*DIM];           // scale * (W_ctx@Wk)^T  [o][i]
__device__ __align__(16) float g_Wcv [DIM*DIM];           // W_ctx@Wv [i][o]
__device__ __align__(16) float g_Wih2[1536*XDIM];         // [W_ih[:, :256] | W_ih[:,256:]@Wo^T]
__device__ __align__(16) float g_bih2[1536];
__device__ __align__(16) float g_cvec[HEADS*DIM];         // scale*WckT@bq (per head)
__device__ __align__(16) float g_colsum[DIM];
__device__ __align__(16) float g_h[2][DIM];
__device__ __align__(16) float g_u[HEADS*DIM];            // [h][i]
__device__ __align__(16) float g_x[XDIM];                 // [a_prev(256) ; v(512)]
__device__ __align__(16) float g_ihh[3072];
__device__ __align__(16) float g_wpart[GRIDF*4096];       // per-block softmax-weighted sums
__device__ float g_mpart[GRIDF*HEADS];
__device__ float g_spart[GRIDF*HEADS];

__device__ __forceinline__ float wred(float a){
    #pragma unroll
    for (int o = 16; o; o >>= 1) a += __shfl_xor_sync(0xffffffffu, a, o);
    return a;
}

// ------------------------------ setup ------------------------------------
__global__ void p0_zero(){ g_colsum[threadIdx.x] = 0.0f; }

// convert F -> bf16 + column sums
__global__ void p1c(const float4* __restrict__ F4){
    int t = threadIdx.x;                      // 128 threads = 128 float4 cols
    float4 acc = make_float4(0.f,0.f,0.f,0.f);
    size_t r0 = (size_t)blockIdx.x * (NFR/128);
    uint2* out = (uint2*)g_Fh;
    for (int r = 0; r < NFR/128; r++){
        size_t row = r0 + r;
        float4 f = F4[row*128 + t];
        acc.x += f.x; acc.y += f.y; acc.z += f.z; acc.w += f.w;
        uint2 pk;
        pk.x = ((unsigned)__bfloat16_as_ushort(__float2bfloat16_rn(f.y)) << 16)
             |  (unsigned)__bfloat16_as_ushort(__float2bfloat16_rn(f.x));
        pk.y = ((unsigned)__bfloat16_as_ushort(__float2bfloat16_rn(f.w)) << 16)
             |  (unsigned)__bfloat16_as_ushort(__float2bfloat16_rn(f.z));
        out[row*128 + t] = pk;
    }
    atomicAdd(&g_colsum[t*4+0], acc.x);
    atomicAdd(&g_colsum[t*4+1], acc.y);
    atomicAdd(&g_colsum[t*4+2], acc.z);
    atomicAdd(&g_colsum[t*4+3], acc.w);
}

// z=0: WckT = scale*(W_ctx@Wk)^T ; z=1: Wcv = W_ctx@Wv
__global__ void p2_gemm(const float* __restrict__ Wctx,
                        const float* __restrict__ Wk,
                        const float* __restrict__ Wv){
    __shared__ float sA[32][33];
    __shared__ float sB[32][33];
    int tx = threadIdx.x, ty = threadIdx.y;
    const float* B = blockIdx.z ? Wv : Wk;
    int i0 = blockIdx.y*32, j0 = blockIdx.x*32;
    float acc[4] = {0.f,0.f,0.f,0.f};
    for (int m0 = 0; m0 < DIM; m0 += 32){
        #pragma unroll
        for (int k = 0; k < 4; k++){
            sA[ty+8*k][tx] = Wctx[(size_t)(i0+ty+8*k)*DIM + m0+tx];
            sB[ty+8*k][tx] = B[(size_t)(m0+ty+8*k)*DIM + j0+tx];
        }
        __syncthreads();
        #pragma unroll
        for (int mm = 0; mm < 32; mm++){
            float b = sB[mm][tx];
            #pragma unroll
            for (int k = 0; k < 4; k++) acc[k] += sA[ty+8*k][mm]*b;
        }
        __syncthreads();
    }
    if (blockIdx.z){
        #pragma unroll
        for (int k = 0; k < 4; k++)
            g_Wcv[(size_t)(i0+ty+8*k)*DIM + j0+tx] = acc[k];
    } else {
        // transpose via smem, scale fold, coalesced store
        __syncthreads();
        #pragma unroll
        for (int k = 0; k < 4; k++) sA[tx][ty+8*k] = acc[k];
        __syncthreads();
        #pragma unroll
        for (int k = 0; k < 4; k++)
            g_WckT[(size_t)(j0+ty+8*k)*DIM + i0+tx] = SCALE*sA[ty+8*k][tx];
    }
}

// Wih2: cols [0,256) copy of W_ih ; cols [256,768): W_ih[:,256:] @ Wo^T
__global__ void p3_wih(const float* __restrict__ W_ih, const float* __restrict__ Wo){
    int tx = threadIdx.x, ty = threadIdx.y;
    int i0 = blockIdx.y*32;
    if (blockIdx.x < 16){
        __shared__ float sA[32][33];
        __shared__ float sB[32][33];
        int j0 = blockIdx.x*32;
        float acc[4] = {0.f,0.f,0.f,0.f};
        for (int m0 = 0; m0 < DIM; m0 += 32){
            #pragma unroll
            for (int k = 0; k < 4; k++){
                sA[ty+8*k][tx] = W_ih[(size_t)(i0+ty+8*k)*XDIM + 256 + m0+tx];
                sB[ty+8*k][tx] = Wo[(size_t)(j0+ty+8*k)*DIM + m0+tx];
            }
            __syncthreads();
            #pragma unroll
            for (int mm = 0; mm < 32; mm++){
                float b = sB[tx][mm];
                #pragma unroll
                for (int k = 0; k < 4; k++) acc[k] += sA[ty+8*k][mm]*b;
            }
            __syncthreads();
        }
        #pragma unroll
        for (int k = 0; k < 4; k++)
            g_Wih2[(size_t)(i0+ty+8*k)*XDIM + 256 + j0+tx] = acc[k];
    } else {
        int c0 = (blockIdx.x-16)*32;
        #pragma unroll
        for (int k = 0; k < 4; k++)
            g_Wih2[(size_t)(i0+ty+8*k)*XDIM + c0+tx] =
                W_ih[(size_t)(i0+ty+8*k)*XDIM + c0+tx];
    }
}

__global__ void p4_vec(const float* __restrict__ Wctx, const float* __restrict__ bctx,
                       const float* __restrict__ Wv,   const float* __restrict__ bv,
                       const float* __restrict__ Wo,   const float* __restrict__ bo,
                       const float* __restrict__ bq,   const float* __restrict__ start,
                       const float* __restrict__ W_ih, const float* __restrict__ b_ih){
    __shared__ float bvp[DIM];
    __shared__ float bo2[DIM];
    int t = threadIdx.x;                      // 512
    float s = 0.f;
    for (int i = 0; i < DIM; i++) s += bctx[i]*Wv[(size_t)i*DIM + t];
    bvp[t] = s + bv[t];
    __syncthreads();
    float s2 = 0.f;
    for (int k = 0; k < DIM; k++) s2 += bvp[k]*Wo[(size_t)k*DIM + t];
    bo2[t] = s2 + bo[t];
    __syncthreads();
    float s3 = 0.f;
    const float inv = 1.0f/(float)NFR;
    for (int i = 0; i < DIM; i++) s3 += (g_colsum[i]*inv)*Wctx[(size_t)i*DIM + t];
    g_h[0][t] = s3 + bctx[t];
    // cvec (scale already folded in WckT)
    for (int r = t; r < HEADS*DIM; r += DIM){
        int h = r >> 9, i = r & 511;
        float s4 = 0.f;
        #pragma unroll 8
        for (int d = 0; d < 64; d++)
            s4 += g_WckT[(size_t)(h*64+d)*DIM + i]*bq[h*64 + d];
        g_cvec[r] = s4;
    }
    // bih2 = b_ih + W_ih[:,256:] @ bo2
    for (int r = t; r < 1536; r += DIM){
        float a = b_ih[r];
        for (int j = 0; j < DIM; j++) a += W_ih[(size_t)r*XDIM + 256 + j]*bo2[j];
        g_bih2[r] = a;
    }
    if (t < ATTR) g_x[t] = start[t];
}

// ----------------------------- per-step ----------------------------------
// block h: q_h = Wq_h^T @ h ; u_h = WckT_h @ q_h + cvec_h ; zero v slice
__global__ void s1_u(const float* __restrict__ Wq, int p){
    __shared__ float spq[4][64];
    __shared__ float sq[64];
    const int h = blockIdx.x, tid = threadIdx.x;
    if (tid < 64) g_x[256 + h*64 + tid] = 0.f;
    const int d = tid & 63, ic = tid >> 6;
    float a = 0.f;
    #pragma unroll 4
    for (int ii = 0; ii < 128; ii++){
        int i = ic*128 + ii;
        a += g_h[p][i] * Wq[(size_t)i*DIM + h*64 + d];
    }
    spq[ic][d] = a;
    __syncthreads();
    if (tid < 64) sq[tid] = spq[0][tid]+spq[1][tid]+spq[2][tid]+spq[3][tid];
    __syncthreads();
    for (int i = tid; i < DIM; i += 256){
        float acc = g_cvec[h*DIM + i];
        #pragma unroll 8
        for (int dd = 0; dd < 64; dd++)
            acc += sq[dd]*g_WckT[(size_t)(h*64+dd)*DIM + i];
        g_u[h*DIM + i] = acc;
    }
}

// fused single-pass flash softmax + weighted frame sum (bf16 frames)
__global__ void __launch_bounds__(256,1) s2f(){
    const int tid = threadIdx.x, warp = tid>>5, lane = tid&31;
    const int hside = warp & 1;               // heads [4*hside, 4*hside+4)
    const int pair  = (blockIdx.x<<2) + (warp>>1);
    const int npairs = GRIDF*4;

    __align__(16) float u[4][16];
    __align__(16) float acc[4][16];
    float m[4], s[4];
    #pragma unroll
    for (int hh = 0; hh < 4; hh++){
        const float4* U4 = (const float4*)(g_u + (size_t)(hside*4+hh)*DIM + lane*16);
        #pragma unroll
        for (int k = 0; k < 4; k++) ((float4*)u[hh])[k] = U4[k];
        #pragma unroll
        for (int k = 0; k < 16; k++) acc[hh][k] = 0.f;
        m[hh] = -3.0e38f; s[hh] = 0.f;
    }

    const uint4* F16 = (const uint4*)g_Fh;
    for (int n = pair; n < NFR; n += npairs){
        uint4 r0 = F16[(size_t)n*64 + 2*lane];
        uint4 r1 = F16[(size_t)n*64 + 2*lane + 1];
        float f[16];
        {
            unsigned w;
            w = r0.x; f[0]=__uint_as_float(w<<16); f[1]=__uint_as_float(w&0xffff0000u);
            w = r0.y; f[2]=__uint_as_float(w<<16); f[3]=__uint_as_float(w&0xffff0000u);
            w = r0.z; f[4]=__uint_as_float(w<<16); f[5]=__uint_as_float(w&0xffff0000u);
            w = r0.w; f[6]=__uint_as_float(w<<16); f[7]=__uint_as_float(w&0xffff0000u);
            w = r1.x; f[8]=__uint_as_float(w<<16); f[9]=__uint_as_float(w&0xffff0000u);
            w = r1.y; f[10]=__uint_as_float(w<<16); f[11]=__uint_as_float(w&0xffff0000u);
            w = r1.z; f[12]=__uint_as_float(w<<16); f[13]=__uint_as_float(w&0xffff0000u);
            w = r1.w; f[14]=__uint_as_float(w<<16); f[15]=__uint_as_float(w&0xffff0000u);
        }
        #pragma unroll
        for (int hh = 0; hh < 4; hh++){
            float l = 0.f;
            #pragma unroll
            for (int k = 0; k < 16; k++) l += u[hh][k]*f[k];
            l = wred(l);                         // all lanes hold the logit
            if (l > m[hh]){                      // warp-uniform branch
                float sc = __expf(m[hh] - l);
                s[hh] *= sc;
                #pragma unroll
                for (int k = 0; k < 16; k++) acc[hh][k] *= sc;
                m[hh] = l;
            }
            float e = __expf(l - m[hh]);
            s[hh] += e;
            #pragma unroll
            for (int k = 0; k < 16; k++) acc[hh][k] += e*f[k];
        }
    }

    // block-level combine: align 4 warps per head-group to block max
    __shared__ float smm[8][4], sms[8][4], smb[8];
    __shared__ __align__(16) float sw[4096];
    if (lane == 0){
        #pragma unroll
        for (int hh = 0; hh < 4; hh++) smm[warp][hh] = m[hh];
    }
    __syncthreads();
    if (tid < 8){
        int hs = tid>>2, hh = tid&3;
        float mb = -3.0e38f;
        #pragma unroll
        for (int wp = 0; wp < 4; wp++) mb = fmaxf(mb, smm[wp*2+hs][hh]);
        smb[tid] = mb;
    }
    for (int i = tid; i < 4096; i += 256) sw[i] = 0.f;
    __syncthreads();
    float sc4[4];
    #pragma unroll
    for (int hh = 0; hh < 4; hh++) sc4[hh] = __expf(m[hh] - smb[hside*4+hh]);
    if (lane == 0){
        #pragma unroll
        for (int hh = 0; hh < 4; hh++) sms[warp][hh] = s[hh]*sc4[hh];
    }
    float4* sw4 = (float4*)sw;
    for (int wp = 0; wp < 4; wp++){
        if ((warp>>1) == wp){
            #pragma unroll
            for (int hh = 0; hh < 4; hh++){
                int base = (hside*4+hh)*128 + lane*4;
                #pragma unroll
                for (int k = 0; k < 4; k++){
                    float4 v = sw4[base+k];
                    float4 a = ((float4*)acc[hh])[k];
                    v.x += a.x*sc4[hh]; v.y += a.y*sc4[hh];
                    v.z += a.z*sc4[hh]; v.w += a.w*sc4[hh];
                    sw4[base+k] = v;
                }
            }
        }
        __syncthreads();
    }
    float* op = g_wpart + (size_t)blockIdx.x*4096;
    for (int i = tid; i < 4096; i += 256) op[i] = sw[i];
    if (tid < 8){
        int hs = tid>>2, hh = tid&3;
        float ssum = 0.f;
        #pragma unroll
        for (int wp = 0; wp < 4; wp++) ssum += sms[wp*2+hs][hh];
        g_spart[blockIdx.x*8 + tid] = ssum;
        g_mpart[blockIdx.x*8 + tid] = smb[tid];
    }
}

// combine partials -> c ; v += c@Wcv (into g_x[256:768])
__global__ void s3c(){
    __shared__ float sM[8], sS[8];
    __shared__ float sef[GRIDF*8];
    __shared__ float sc[256];
    __shared__ float sv[4][64];
    const int tid = threadIdx.x, bi = blockIdx.x;
    for (int i = tid; i < GRIDF*8; i += 256) sef[i] = g_mpart[i];
    __syncthreads();
    if (tid < 8){
        float M = -3.0e38f;
        for (int b = 0; b < GRIDF; b++) M = fmaxf(M, sef[b*8+tid]);
        sM[tid] = M;
    }
    __syncthreads();
    for (int i = tid; i < GRIDF*8; i += 256) sef[i] = __expf(sef[i] - sM[i&7]);
    __syncthreads();
    if (tid < 8){
        float S = 0.f;
        for (int b = 0; b < GRIDF; b++) S += g_spart[b*8+tid]*sef[b*8+tid];
        sS[tid] = S;
    }
    __syncthreads();
    const int idx = bi*256 + tid;
    const int hb = bi >> 1;
    {
        float a = 0.f;
        #pragma unroll 4
        for (int b = 0; b < GRIDF; b++) a += g_wpart[(size_t)b*4096 + idx]*sef[b*8+hb];
        sc[tid] = a / sS[hb];
    }
    __syncthreads();
    const int d = tid & 63, isub = tid >> 6;
    const int i0 = (bi & 1)*256;
    float pv = 0.f;
    #pragma unroll 8
    for (int ii = 0; ii < 64; ii++){
        int i = i0 + isub*64 + ii;
        pv += sc[isub*64+ii]*g_Wcv[(size_t)i*DIM + hb*64 + d];
    }
    sv[isub][d] = pv;
    __syncthreads();
    if (tid < 64)
        atomicAdd(&g_x[256 + hb*64 + tid],
                  sv[0][tid]+sv[1][tid]+sv[2][tid]+sv[3][tid]);
}

// GRU matvecs: ih = Wih2@[a;v] + bih2 ; hh = W_hh@h
__global__ void s5_gru(const float* __restrict__ W_hh, int p){
    const int warp = threadIdx.x >> 5, lane = threadIdx.x & 31;
    const int gw = blockIdx.x*8 + warp, nw = gridDim.x*8;
    for (int r = gw; r < 3072; r += nw){
        float a = 0.f;
        if (r < 1536){
            const float4* W = (const float4*)(g_Wih2 + (size_t)r*XDIM);
            const float4* X = (const float4*)g_x;
            #pragma unroll
            for (int k = 0; k < 6; k++){
                float4 w = W[lane + 32*k], x = X[lane + 32*k];
                a += w.x*x.x + w.y*x.y + w.z*x.z + w.w*x.w;
            }
            a = wred(a);
            if (lane == 0) g_ihh[r] = a + g_bih2[r];
        } else {
            int rr = r - 1536;
            const float4* W = (const float4*)(W_hh + (size_t)rr*DIM);
            const float4* H = (const float4*)g_h[p];
            #pragma unroll
            for (int k = 0; k < 4; k++){
                float4 w = W[lane + 32*k], h = H[lane + 32*k];
                a += w.x*h.x + w.y*h.y + w.z*h.z + w.w*h.w;
            }
            a = wred(a);
            if (lane == 0) g_ihh[r] = a;
        }
    }
}

// gates + heads + output
__global__ void s6_fin(int p, int step, float* __restrict__ out,
                       const float* __restrict__ b_hn,
                       const float* __restrict__ W_attr, const float* __restrict__ b_attr,
                       const float* __restrict__ W_conf, const float* __restrict__ b_conf){
    __shared__ __align__(16) float hn[DIM];
    const int tid = threadIdx.x;
    for (int j = tid; j < DIM; j += 256){
        float ihr = g_ihh[j],      ihz = g_ihh[512+j],  ihn = g_ihh[1024+j];
        float hhr = g_ihh[1536+j], hhz = g_ihh[2048+j], hhn = g_ihh[2560+j];
        float r = 1.0f/(1.0f + expf(-(ihr + hhr)));
        float z = 1.0f/(1.0f + expf(-(ihz + hhz)));
        float nn = tanhf(ihn + r*(hhn + b_hn[j]));
        float h = (1.0f - z)*nn + z*g_h[p][j];
        hn[j] = h;
        if (blockIdx.x == 0) g_h[1-p][j] = h;
    }
    __syncthreads();
    const int warp = tid >> 5, lane = tid & 31;
    const int gw = blockIdx.x*8 + warp;        // 0..127
    const float4* H4 = (const float4*)hn;
    float4 hv[4];
    #pragma unroll
    for (int k = 0; k < 4; k++) hv[k] = H4[lane + 32*k];
    #pragma unroll
    for (int rr = 0; rr < 2; rr++){
        int row = gw*2 + rr;                   // 0..255
        const float4* W = (const float4*)(W_attr + (size_t)row*DIM);
        float a = 0.f;
        #pragma unroll
        for (int k = 0; k < 4; k++){
            float4 w = W[lane + 32*k];
            a += w.x*hv[k].x + w.y*hv[k].y + w.z*hv[k].z + w.w*hv[k].w;
        }
        a = wred(a);
        if (lane == 0){
            float v = a + b_attr[row];
            out[step*ATTR + row] = v;
            g_x[row] = v;
        }
    }
    if (gw == 0){
        const float4* W = (const float4*)W_conf;
        float a = 0.f;
        #pragma unroll
        for (int k = 0; k < 4; k++){
            float4 w = W[lane + 32*k];
            a += w.x*hv[k].x + w.y*hv[k].y + w.z*hv[k].z + w.w*hv[k].w;
        }
        a = wred(a);
        if (lane == 0)
            out[KSTEPS*ATTR + step] = 1.0f/(1.0f + expf(-(a + b_conf[0])));
    }
}

// ------------------------------- launch -----------------------------------
extern "C" void kernel_launch(void* const* d_in, const int* in_sizes, int n_in,
                              void* d_out, int out_size){
    const float* F      = (const float*)d_in[0];
    const float* Wctx   = (const float*)d_in[1];
    const float* bctx   = (const float*)d_in[2];
    const float* Wq     = (const float*)d_in[3];
    const float* bq     = (const float*)d_in[4];
    const float* Wk     = (const float*)d_in[5];
    // d_in[6] = bk : softmax-invariant, unused
    const float* Wv     = (const float*)d_in[7];
    const float* bv     = (const float*)d_in[8];
    const float* Wo     = (const float*)d_in[9];
    const float* bo     = (const float*)d_in[10];
    const float* W_ih   = (const float*)d_in[11];
    const float* W_hh   = (const float*)d_in[12];
    const float* b_ih   = (const float*)d_in[13];
    const float* b_hn   = (const float*)d_in[14];
    const float* start  = (const float*)d_in[15];
    const float* W_attr = (const float*)d_in[16];
    const float* b_attr = (const float*)d_in[17];
    const float* W_conf = (const float*)d_in[18];
    const float* b_conf = (const float*)d_in[19];
    float* out = (float*)d_out;

    p0_zero<<<1, 512>>>();
    p1c<<<128, 128>>>((const float4*)F);
    p2_gemm<<<dim3(16,16,2), dim3(32,8)>>>(Wctx, Wk, Wv);
    p3_wih<<<dim3(24,48), dim3(32,8)>>>(W_ih, Wo);
    p4_vec<<<1, 512>>>(Wctx, bctx, Wv, bv, Wo, bo, bq, start, W_ih, b_ih);

    for (int step = 0; step < KSTEPS; step++){
        int p = step & 1;
        s1_u<<<8, 256>>>(Wq, p);
        s2f<<<GRIDF, 256>>>();
        s3c<<<16, 256>>>();
        s5_gru<<<96, 256>>>(W_hh, p);
        s6_fin<<<16, 256>>>(p, step, out, b_hn, W_attr, b_attr, W_conf, b_conf);
    }
}